// round 11
// baseline (speedup 1.0000x reference)
#include <cuda_runtime.h>
#include <cstdint>

#define GIBBS_K   10
#define BATCH     65536
#define PAIRS     32768          // BATCH/2 : warp handles (b, b+PAIRS)
#define WPB       16
#define TPB       (WPB*32)       // 512

#define HALF_H 8388608u
#define HALF_V 2097152u

#define TW_ROWF4      40                       // float4 per wh row (640B = 5*128)
#define TW_ROW_BYTES  (TW_ROWF4*16)
#define SMEM_TF_BYTES 65536                    // wv radix-64: 64n x 64o x float4
#define SMEM_TW_BYTES (4*64*TW_ROWF4*16)       // 163840
#define SMEM_BYTES    (SMEM_TF_BYTES + SMEM_TW_BYTES)   // 229376

#define NEG_L2E (-1.4426950408889634f)

typedef unsigned long long u64;

struct RbmKeys { uint2 kh[GIBBS_K]; uint2 kv[GIBBS_K]; };

__device__ double   g_rbm_sum = 0.0;
__device__ unsigned g_rbm_cnt = 0u;
__device__ float4   gTf[64 * 64];
__device__ float4   gTw[4 * 64 * TW_ROWF4];

// ---------------- JAX threefry2x32 (exact) ----------------
__host__ __device__ __forceinline__ unsigned rbm_rotl32(unsigned x, int r) {
#ifdef __CUDA_ARCH__
    return __funnelshift_l(x, x, r);
#else
    return (x << r) | (x >> (32 - r));
#endif
}

__host__ __device__ __forceinline__ void rbm_tf2x32(unsigned k0, unsigned k1,
                                                    unsigned x0, unsigned x1,
                                                    unsigned& o0, unsigned& o1) {
    unsigned ks2 = k0 ^ k1 ^ 0x1BD11BDAu;
    x0 += k0; x1 += k1;
#define TFR(r) { x0 += x1; x1 = rbm_rotl32(x1, r); x1 ^= x0; }
    TFR(13) TFR(15) TFR(26) TFR(6)
    x0 += k1;  x1 += ks2 + 1u;
    TFR(17) TFR(29) TFR(16) TFR(24)
    x0 += ks2; x1 += k0 + 2u;
    TFR(13) TFR(15) TFR(26) TFR(6)
    x0 += k0;  x1 += k1 + 3u;
    TFR(17) TFR(29) TFR(16) TFR(24)
    x0 += k1;  x1 += ks2 + 4u;
    TFR(13) TFR(15) TFR(26) TFR(6)
    x0 += ks2; x1 += k0 + 5u;
#undef TFR
    o0 = x0; o1 = x1;
}

__device__ __forceinline__ float rbm_u01(unsigned b) {
    return __uint_as_float((b >> 9) | 0x3f800000u) - 1.0f;
}
__device__ __forceinline__ float rbm_softplus(float x) {
    return fmaxf(x, 0.0f) + log1pf(expf(-fabsf(x)));
}
__device__ __forceinline__ float rbm_warp_sum(float v) {
    #pragma unroll
    for (int s = 16; s > 0; s >>= 1) v += __shfl_xor_sync(0xffffffffu, v, s);
    return v;
}
__device__ __forceinline__ void rbm_unpack2(u64 p, float& lo, float& hi) {
    asm("mov.b64 {%0, %1}, %2;" : "=f"(lo), "=f"(hi) : "l"(p));
}
__device__ __forceinline__ u64 rbm_addx2(u64 a, u64 b) {
    u64 r; asm("add.rn.f32x2 %0, %1, %2;" : "=l"(r) : "l"(a), "l"(b)); return r;
}
__device__ __forceinline__ float rbm_ex2(float x) {
    float r; asm("ex2.approx.f32 %0, %1;" : "=f"(r) : "f"(x)); return r;
}
__device__ __forceinline__ float rbm_nexp(float x, float nc) {
    return rbm_ex2(fmaf(x, NEG_L2E, nc));
}
__device__ __forceinline__ bool rbm_draw(unsigned bits, float e) {
    float u = rbm_u01(bits);
    return fmaf(u, e, u) < 1.0f;
}

// wh slot swizzle: injective into 0..32; bank-group = slot mod 8 is
// all-distinct over any stride-2 8-window of g.
__host__ __device__ __forceinline__ int rbm_slot(int g) {
    return g + 9 * ((g >> 3) & 1) - 8 * ((g >> 4) & 1);
}

// ---------------------------------------------------------------------------
// Build LUTs once.
// gTf[n*64+o].a = sum_{t<6} bit_t(n) * K[a][(o+t)&63]
// gTw[(a*64+n)*40 + slot(g)].k = sum_{t<6} bit_t(n) * K[a][(2g+k-1-t)&63]
// ---------------------------------------------------------------------------
__global__ void rbm_build_tables(const float* __restrict__ kern) {
    const int tid = threadIdx.x;
    for (int idx = tid; idx < 64 * 64; idx += 256) {
        int o = idx & 63, n = idx >> 6;
        float4 s = make_float4(0.f, 0.f, 0.f, 0.f);
        #pragma unroll
        for (int t = 0; t < 6; t++) {
            if ((n >> t) & 1) {
                int j = (o + t) & 63;
                s.x += kern[j];
                s.y += kern[64 + j];
                s.z += kern[128 + j];
                s.w += kern[192 + j];
            }
        }
        gTf[idx] = s;
    }
    for (int i2 = tid; i2 < 4 * 64 * 32; i2 += 256) {
        int g = i2 & 31, n = (i2 >> 5) & 63, a = i2 >> 11;
        float4 E = make_float4(0.f, 0.f, 0.f, 0.f);
        #pragma unroll
        for (int t = 0; t < 6; t++) {
            if ((n >> t) & 1) {
                E.x += kern[a * 64 + ((2 * g + 0 - 1 - t + 128) & 63)];
                E.y += kern[a * 64 + ((2 * g + 1 - 1 - t + 128) & 63)];
                E.z += kern[a * 64 + ((2 * g + 2 - 1 - t + 128) & 63)];
                E.w += kern[a * 64 + ((2 * g + 3 - 1 - t + 128) & 63)];
            }
        }
        gTw[(a * 64 + n) * TW_ROWF4 + rbm_slot(g)] = E;
    }
}

// wv radix-64: 11 chunks of 6 bits.
__device__ __forceinline__ void rbm_wv64(u64 v, int lane,
                                         const ulonglong2* __restrict__ Tf,
                                         u64 P[4]) {
    P[0] = 0ull; P[1] = 0ull; P[2] = 0ull; P[3] = 0ull;
    int off = (-lane) & 63;
    #pragma unroll
    for (int c = 0; c < 11; c++) {
        unsigned n = (unsigned)(v >> (6 * c)) & 63u;
        int idx = (int)n * 64 + off;
        ulonglong2 A = Tf[idx];
        ulonglong2 B = Tf[idx ^ 32];
        P[0] = rbm_addx2(P[0], A.x);
        P[1] = rbm_addx2(P[1], A.y);
        P[2] = rbm_addx2(P[2], B.x);
        P[3] = rbm_addx2(P[3], B.y);
        off = (off + 6) & 63;
    }
}

// wh: half-warp per sample; lane (j = lane&15) accumulates outputs
// {4j..4j+3} of its sample via one LDS.128 per (c,a). g=(2j-3c)&31.
__device__ __forceinline__ void rbm_whq(const u64 hs[4], int lane,
                                        const char* __restrict__ Tw,
                                        u64& QA, u64& QB) {
    const int j2 = (lane & 15) * 2;
    QA = 0ull; QB = 0ull;
    #pragma unroll
    for (int c = 0; c < 11; c++) {
        int g = (j2 + ((96 - 3 * c) & 31)) & 31;
        const char* base = Tw + rbm_slot(g) * 16;
        #pragma unroll
        for (int a = 0; a < 4; a++) {
            unsigned n = (unsigned)(hs[a] >> (6 * c)) & 63u;
            ulonglong2 E = *(const ulonglong2*)(base + (a * 64 + (int)n) * TW_ROW_BYTES);
            QA = rbm_addx2(QA, E.x);
            QB = rbm_addx2(QB, E.y);
        }
    }
}

__device__ __forceinline__ float rbm_fe_from(const u64 P[4], u64 v,
                                             const float* __restrict__ csh,
                                             float bsc) {
    float a0, a1, a2, a3, b0, b1, b2, b3;
    rbm_unpack2(P[0], a0, a1);
    rbm_unpack2(P[1], a2, a3);
    rbm_unpack2(P[2], b0, b1);
    rbm_unpack2(P[3], b2, b3);
    float s = rbm_softplus(a0 + csh[0]) + rbm_softplus(b0 + csh[0])
            + rbm_softplus(a1 + csh[1]) + rbm_softplus(b1 + csh[1])
            + rbm_softplus(a2 + csh[2]) + rbm_softplus(b2 + csh[2])
            + rbm_softplus(a3 + csh[3]) + rbm_softplus(b3 + csh[3]);
    s = rbm_warp_sum(s);
    return -bsc * (float)__popcll(v) - s;
}

// ---------------------------------------------------------------------------
// Persistent kernel: grid = #SMs; each warp strides over sample pairs.
// ---------------------------------------------------------------------------
__global__ void __launch_bounds__(TPB, 1)
rbm_gibbs_kernel(float* __restrict__ out,
                 const float* __restrict__ v_data,
                 const float* __restrict__ b_scalar,
                 const float* __restrict__ c_vector,
                 RbmKeys keys) {
    extern __shared__ char smem_dyn[];
    ulonglong2* Tf = (ulonglong2*)smem_dyn;
    char*       Tw = smem_dyn + SMEM_TF_BYTES;
    __shared__ float  csh[4];
    __shared__ double wsum[WPB];

    const int tid  = threadIdx.x;
    const int lane = tid & 31;
    const int wid  = tid >> 5;

    {   // one-time table copy per block lifetime
        float4* sf = (float4*)smem_dyn;
        for (int i = tid; i < 64 * 64; i += TPB) sf[i] = gTf[i];
        float4* sw = (float4*)Tw;
        for (int i = tid; i < 4 * 64 * TW_ROWF4; i += TPB) sw[i] = gTw[i];
    }
    if (tid < 4) csh[tid] = c_vector[tid];
    __syncthreads();

    const float bsc = b_scalar[0];
    const float nb  = bsc * NEG_L2E;
    float nca[4];
    #pragma unroll
    for (int a = 0; a < 4; a++) nca[a] = csh[a] * NEG_L2E;

    const int stride = gridDim.x * WPB;
    double dsum = 0.0;

    for (int w = blockIdx.x * WPB + wid; w < PAIRS; w += stride) {
        const int b0 = w;
        const int b1 = w + PAIRS;

        u64 v0, v1;
        {
            float a0 = v_data[(size_t)b0 * 64 + lane];
            float a1 = v_data[(size_t)b0 * 64 + lane + 32];
            unsigned lo = __ballot_sync(0xffffffffu, a0 != 0.0f);
            unsigned hi = __ballot_sync(0xffffffffu, a1 != 0.0f);
            v0 = (u64)lo | ((u64)hi << 32);
            float c0 = v_data[(size_t)b1 * 64 + lane];
            float c1 = v_data[(size_t)b1 * 64 + lane + 32];
            lo = __ballot_sync(0xffffffffu, c0 != 0.0f);
            hi = __ballot_sync(0xffffffffu, c1 != 0.0f);
            v1 = (u64)lo | ((u64)hi << 32);
        }

        u64 P0[4], P1[4];
        rbm_wv64(v0, lane, Tf, P0);
        rbm_wv64(v1, lane, Tf, P1);
        const float fed0 = rbm_fe_from(P0, v0, csh, bsc);
        const float fed1 = rbm_fe_from(P1, v1, csh, bsc);

        const unsigned baseH = (unsigned)b0 * 256u;
        const unsigned baseV = (unsigned)b0 * 64u + (unsigned)lane;

        #pragma unroll 1
        for (int t = 0; t < GIBBS_K; t++) {
            if (t) {
                rbm_wv64(v0, lane, Tf, P0);
                rbm_wv64(v1, lane, Tf, P1);
            }

            float e0[8], e1[8];
            {
                float x, y;
                rbm_unpack2(P0[0], x, y); e0[0] = rbm_nexp(x, nca[0]); e0[2] = rbm_nexp(y, nca[1]);
                rbm_unpack2(P0[1], x, y); e0[4] = rbm_nexp(x, nca[2]); e0[6] = rbm_nexp(y, nca[3]);
                rbm_unpack2(P0[2], x, y); e0[1] = rbm_nexp(x, nca[0]); e0[3] = rbm_nexp(y, nca[1]);
                rbm_unpack2(P0[3], x, y); e0[5] = rbm_nexp(x, nca[2]); e0[7] = rbm_nexp(y, nca[3]);
                rbm_unpack2(P1[0], x, y); e1[0] = rbm_nexp(x, nca[0]); e1[2] = rbm_nexp(y, nca[1]);
                rbm_unpack2(P1[1], x, y); e1[4] = rbm_nexp(x, nca[2]); e1[6] = rbm_nexp(y, nca[3]);
                rbm_unpack2(P1[2], x, y); e1[1] = rbm_nexp(x, nca[0]); e1[3] = rbm_nexp(y, nca[1]);
                rbm_unpack2(P1[3], x, y); e1[5] = rbm_nexp(x, nca[2]); e1[7] = rbm_nexp(y, nca[3]);
            }

            const uint2 kh = keys.kh[t];
            u64 h0[4], h1[4];
            #pragma unroll
            for (int a = 0; a < 4; a++) {
                unsigned cA = baseH + (unsigned)(a * 64 + lane);
                unsigned cB = cA + 32u;
                unsigned rA0, rA1, rB0, rB1;
                rbm_tf2x32(kh.x, kh.y, cA, cA + HALF_H, rA0, rA1);
                rbm_tf2x32(kh.x, kh.y, cB, cB + HALF_H, rB0, rB1);
                unsigned l0 = __ballot_sync(0xffffffffu, rbm_draw(rA0, e0[a * 2 + 0]));
                unsigned g0 = __ballot_sync(0xffffffffu, rbm_draw(rB0, e0[a * 2 + 1]));
                unsigned l1 = __ballot_sync(0xffffffffu, rbm_draw(rA1, e1[a * 2 + 0]));
                unsigned g1 = __ballot_sync(0xffffffffu, rbm_draw(rB1, e1[a * 2 + 1]));
                h0[a] = (u64)l0 | ((u64)g0 << 32);
                h1[a] = (u64)l1 | ((u64)g1 << 32);
            }

            // per-lane sample select, then 4-output wh
            u64 hs[4];
            #pragma unroll
            for (int a = 0; a < 4; a++) hs[a] = (lane & 16) ? h1[a] : h0[a];
            u64 QA, QB;
            rbm_whq(hs, lane, Tw, QA, QB);

            // gather: lane l needs wh_s0[l], wh_s0[l+32], wh_s1[l], wh_s1[l+32]
            float r0, r1, r2, r3;
            rbm_unpack2(QA, r0, r1);
            rbm_unpack2(QB, r2, r3);
            const int s0 = lane >> 2;
            float A0 = __shfl_sync(0xffffffffu, r0, s0);
            float A1 = __shfl_sync(0xffffffffu, r1, s0);
            float A2 = __shfl_sync(0xffffffffu, r2, s0);
            float A3 = __shfl_sync(0xffffffffu, r3, s0);
            float B0 = __shfl_sync(0xffffffffu, r0, s0 + 8);
            float B1 = __shfl_sync(0xffffffffu, r1, s0 + 8);
            float B2 = __shfl_sync(0xffffffffu, r2, s0 + 8);
            float B3 = __shfl_sync(0xffffffffu, r3, s0 + 8);
            float C0 = __shfl_sync(0xffffffffu, r0, s0 + 16);
            float C1 = __shfl_sync(0xffffffffu, r1, s0 + 16);
            float C2 = __shfl_sync(0xffffffffu, r2, s0 + 16);
            float C3 = __shfl_sync(0xffffffffu, r3, s0 + 16);
            float D0 = __shfl_sync(0xffffffffu, r0, s0 + 24);
            float D1 = __shfl_sync(0xffffffffu, r1, s0 + 24);
            float D2 = __shfl_sync(0xffffffffu, r2, s0 + 24);
            float D3 = __shfl_sync(0xffffffffu, r3, s0 + 24);
            const bool k1 = (lane & 1), k2 = (lane & 2);
            float wh00 = k2 ? (k1 ? A3 : A2) : (k1 ? A1 : A0);
            float wh01 = k2 ? (k1 ? B3 : B2) : (k1 ? B1 : B0);
            float wh10 = k2 ? (k1 ? C3 : C2) : (k1 ? C1 : C0);
            float wh11 = k2 ? (k1 ? D3 : D2) : (k1 ? D1 : D0);

            float ev00 = rbm_nexp(wh00, nb);
            float ev01 = rbm_nexp(wh01, nb);
            float ev10 = rbm_nexp(wh10, nb);
            float ev11 = rbm_nexp(wh11, nb);

            const uint2 kv = keys.kv[t];
            unsigned r00, r01, r10, r11;
            rbm_tf2x32(kv.x, kv.y, baseV,       baseV + HALF_V,       r00, r01);
            rbm_tf2x32(kv.x, kv.y, baseV + 32u, baseV + 32u + HALF_V, r10, r11);
            unsigned m0l = __ballot_sync(0xffffffffu, rbm_draw(r00, ev00));
            unsigned m0h = __ballot_sync(0xffffffffu, rbm_draw(r10, ev01));
            unsigned m1l = __ballot_sync(0xffffffffu, rbm_draw(r01, ev10));
            unsigned m1h = __ballot_sync(0xffffffffu, rbm_draw(r11, ev11));
            v0 = (u64)m0l | ((u64)m0h << 32);
            v1 = (u64)m1l | ((u64)m1h << 32);
        }

        u64 Q0[4], Q1[4];
        rbm_wv64(v0, lane, Tf, Q0);
        rbm_wv64(v1, lane, Tf, Q1);
        const float fem0 = rbm_fe_from(Q0, v0, csh, bsc);
        const float fem1 = rbm_fe_from(Q1, v1, csh, bsc);
        dsum += (double)((fed0 - fem0) + (fed1 - fem1));
    }

    if (lane == 0) wsum[wid] = dsum;
    __syncthreads();
    if (tid == 0) {
        double s = 0.0;
        #pragma unroll
        for (int i = 0; i < WPB; i++) s += wsum[i];
        atomicAdd(&g_rbm_sum, s);
        __threadfence();
        unsigned ticket = atomicAdd(&g_rbm_cnt, 1u);
        if (ticket == gridDim.x - 1) {
            __threadfence();
            double total = atomicAdd(&g_rbm_sum, 0.0);
            out[0] = (float)(total / (double)BATCH);
            g_rbm_sum = 0.0;        // reset for next graph replay
            g_rbm_cnt = 0u;
        }
    }
}

// ---------------------------------------------------------------------------
// Host: replicate scan key-split chain: key(42); per step k,kh,kv = split(k,3)
// ---------------------------------------------------------------------------
extern "C" void kernel_launch(void* const* d_in, const int* in_sizes, int n_in,
                              void* d_out, int out_size) {
    const float* v_data   = (const float*)d_in[0];
    const float* kern     = (const float*)d_in[1];
    const float* b_scalar = (const float*)d_in[2];
    const float* c_vector = (const float*)d_in[3];

    RbmKeys keys;
    unsigned k0 = 0u, k1 = 42u;
    for (int t = 0; t < GIBBS_K; t++) {
        unsigned A0, B0, A1, B1, A2, B2;
        rbm_tf2x32(k0, k1, 0u, 3u, A0, B0);
        rbm_tf2x32(k0, k1, 1u, 4u, A1, B1);
        rbm_tf2x32(k0, k1, 2u, 5u, A2, B2);
        keys.kh[t] = make_uint2(A2, B0);  // keys[1]
        keys.kv[t] = make_uint2(B1, B2);  // keys[2]
        k0 = A0; k1 = A1;                 // carried key
    }

    int nsm = 0;
    cudaDeviceGetAttribute(&nsm, cudaDevAttrMultiProcessorCount, 0);
    if (nsm <= 0) nsm = 148;

    cudaFuncSetAttribute(rbm_gibbs_kernel,
                         cudaFuncAttributeMaxDynamicSharedMemorySize, SMEM_BYTES);

    rbm_build_tables<<<1, 256>>>(kern);
    rbm_gibbs_kernel<<<nsm, TPB, SMEM_BYTES>>>((float*)d_out, v_data,
                                               b_scalar, c_vector, keys);
}

// round 12
// speedup vs baseline: 1.0246x; 1.0246x over previous
#include <cuda_runtime.h>
#include <cstdint>

#define GIBBS_K   10
#define BATCH     65536
#define PAIRS     32768          // BATCH/2 : warp handles (b, b+PAIRS)
#define WPB       8
#define TPB       (WPB*32)       // 256
#define NBLOCKS   (PAIRS/WPB)    // 4096

#define HALF_H 8388608u          // (BATCH*ALPHA*N)/2
#define HALF_V 2097152u          // (BATCH*N)/2

#define SMEM_TF_BYTES 32768      // wv radix-32 table: 32n x 64o x float4
#define SMEM_TQ_BYTES 65536      // wh radix-64 pair table: 4a x 64n x 32p x float2
#define SMEM_BYTES    (SMEM_TF_BYTES + SMEM_TQ_BYTES)

#define NEG_L2E (-1.4426950408889634f)

typedef unsigned long long u64;

struct RbmKeys { uint2 kh[GIBBS_K]; uint2 kv[GIBBS_K]; };

__device__ double   g_rbm_sum = 0.0;
__device__ unsigned g_rbm_cnt = 0u;
__device__ float4   gTf[32 * 64];   // wv: [n][o] -> {a0,a1,a2,a3}
__device__ float4   gTq[4096];      // wh: pairs of float2 entries

// ---------------- JAX threefry2x32 (exact) ----------------
__host__ __device__ __forceinline__ unsigned rbm_rotl32(unsigned x, int r) {
#ifdef __CUDA_ARCH__
    return __funnelshift_l(x, x, r);
#else
    return (x << r) | (x >> (32 - r));
#endif
}

__host__ __device__ __forceinline__ void rbm_tf2x32(unsigned k0, unsigned k1,
                                                    unsigned x0, unsigned x1,
                                                    unsigned& o0, unsigned& o1) {
    unsigned ks2 = k0 ^ k1 ^ 0x1BD11BDAu;
    x0 += k0; x1 += k1;
#define TFR(r) { x0 += x1; x1 = rbm_rotl32(x1, r); x1 ^= x0; }
    TFR(13) TFR(15) TFR(26) TFR(6)
    x0 += k1;  x1 += ks2 + 1u;
    TFR(17) TFR(29) TFR(16) TFR(24)
    x0 += ks2; x1 += k0 + 2u;
    TFR(13) TFR(15) TFR(26) TFR(6)
    x0 += k0;  x1 += k1 + 3u;
    TFR(17) TFR(29) TFR(16) TFR(24)
    x0 += k1;  x1 += ks2 + 4u;
    TFR(13) TFR(15) TFR(26) TFR(6)
    x0 += ks2; x1 += k0 + 5u;
#undef TFR
    o0 = x0; o1 = x1;
}

__device__ __forceinline__ float rbm_u01(unsigned b) {
    return __uint_as_float((b >> 9) | 0x3f800000u) - 1.0f;
}
__device__ __forceinline__ float rbm_softplus(float x) {
    return fmaxf(x, 0.0f) + log1pf(expf(-fabsf(x)));
}
__device__ __forceinline__ float rbm_warp_sum(float v) {
    #pragma unroll
    for (int s = 16; s > 0; s >>= 1) v += __shfl_xor_sync(0xffffffffu, v, s);
    return v;
}
__device__ __forceinline__ void rbm_unpack2(u64 p, float& lo, float& hi) {
    asm("mov.b64 {%0, %1}, %2;" : "=f"(lo), "=f"(hi) : "l"(p));
}
__device__ __forceinline__ u64 rbm_addx2(u64 a, u64 b) {
    u64 r; asm("add.rn.f32x2 %0, %1, %2;" : "=l"(r) : "l"(a), "l"(b)); return r;
}
__device__ __forceinline__ float rbm_ex2(float x) {
    float r; asm("ex2.approx.f32 %0, %1;" : "=f"(r) : "f"(x)); return r;
}
// e = exp(-(x + c)) = ex2(fma(x, -log2e, nc)), nc = -c*log2e precomputed
__device__ __forceinline__ float rbm_nexp(float x, float nc) {
    return rbm_ex2(fmaf(x, NEG_L2E, nc));
}
// Bernoulli: u < 1/(1+e)  <=>  fma(u, e, u) < 1
__device__ __forceinline__ bool rbm_draw(unsigned bits, float e) {
    float u = rbm_u01(bits);
    return fmaf(u, e, u) < 1.0f;
}

// ---------------------------------------------------------------------------
// Pre-kernel: build LUTs once (1 block).
// gTf[n*64+o].a = sum_{t<5} bit_t(n) * K[a][(o+t)&63]          (radix-32 wv)
// gTq entry (a,n,p) float2:                                     (radix-64 wh)
//   e0 = sum_{t<6} bit_t(n) * K[a][(2p-1-t)&63]   (output i=2p)
//   e1 = sum_{t<6} bit_t(n) * K[a][(2p-2-t)&63]   (output i=2p-1)
// ---------------------------------------------------------------------------
__global__ void rbm_build_tables(const float* __restrict__ kern) {
    const int tid = threadIdx.x;
    for (int idx = tid; idx < 32 * 64; idx += 256) {
        int o = idx & 63, n = idx >> 6;
        float4 s = make_float4(0.f, 0.f, 0.f, 0.f);
        #pragma unroll
        for (int t = 0; t < 5; t++) {
            if ((n >> t) & 1) {
                int j = (o + t) & 63;
                s.x += kern[j];
                s.y += kern[64 + j];
                s.z += kern[128 + j];
                s.w += kern[192 + j];
            }
        }
        gTf[idx] = s;
    }
    for (int idx2 = tid; idx2 < 4096; idx2 += 256) {
        int a = idx2 >> 10, n = (idx2 >> 4) & 63, p0 = (idx2 & 15) * 2;
        float4 r = make_float4(0.f, 0.f, 0.f, 0.f);
        #pragma unroll
        for (int t = 0; t < 6; t++) {
            if ((n >> t) & 1) {
                r.x += kern[a * 64 + ((2 * p0 - 1 - t + 128) & 63)];
                r.y += kern[a * 64 + ((2 * p0 - 2 - t + 128) & 63)];
                r.z += kern[a * 64 + ((2 * p0 + 1 - t + 128) & 63)];
                r.w += kern[a * 64 + ((2 * p0 - t + 128) & 63)];
            }
        }
        gTq[idx2] = r;
    }
}

// ---------------------------------------------------------------------------
// wv radix-32: 13 chunks of 5 bits.
// P[0]=(a0,a1)@i0  P[1]=(a2,a3)@i0  P[2]=(a0,a1)@i1  P[3]=(a2,a3)@i1
// ---------------------------------------------------------------------------
__device__ __forceinline__ void rbm_wv32(u64 v, int lane,
                                         const ulonglong2* __restrict__ Tf,
                                         u64 P[4]) {
    P[0] = 0ull; P[1] = 0ull; P[2] = 0ull; P[3] = 0ull;
    int off = (-lane) & 63;
    #pragma unroll
    for (int c = 0; c < 13; c++) {
        unsigned n = (unsigned)(v >> (5 * c)) & 31u;
        int idx = (int)n * 64 + off;
        ulonglong2 A = Tf[idx];
        ulonglong2 B = Tf[idx ^ 32];
        P[0] = rbm_addx2(P[0], A.x);
        P[1] = rbm_addx2(P[1], A.y);
        P[2] = rbm_addx2(P[2], B.x);
        P[3] = rbm_addx2(P[3], B.y);
        off = (off + 5) & 63;
    }
}

// ---------------------------------------------------------------------------
// wh radix-64: 11 chunks of 6 bits per alpha; lane l accumulates packed
// outputs (2l, (2l-1)&63). FOUR accumulators (one per alpha) to shorten
// the dependency chain 44 -> 11; merged with a 3-add tree at the end.
// ---------------------------------------------------------------------------
__device__ __forceinline__ void rbm_wh64(const u64 h[4], int lane,
                                         const u64* __restrict__ Tq,
                                         float& wlo, float& whi) {
    u64 Q0 = 0ull, Q1 = 0ull, Q2 = 0ull, Q3 = 0ull;
    int p = lane;
    #pragma unroll
    for (int c = 0; c < 11; c++) {
        unsigned n0 = (unsigned)(h[0] >> (6 * c)) & 63u;
        unsigned n1 = (unsigned)(h[1] >> (6 * c)) & 63u;
        unsigned n2 = (unsigned)(h[2] >> (6 * c)) & 63u;
        unsigned n3 = (unsigned)(h[3] >> (6 * c)) & 63u;
        Q0 = rbm_addx2(Q0, Tq[(0 * 64 + (int)n0) * 32 + p]);
        Q1 = rbm_addx2(Q1, Tq[(1 * 64 + (int)n1) * 32 + p]);
        Q2 = rbm_addx2(Q2, Tq[(2 * 64 + (int)n2) * 32 + p]);
        Q3 = rbm_addx2(Q3, Tq[(3 * 64 + (int)n3) * 32 + p]);
        p = (p + 29) & 31;   // -3 mod 32
    }
    u64 Q = rbm_addx2(rbm_addx2(Q0, Q1), rbm_addx2(Q2, Q3));
    rbm_unpack2(Q, wlo, whi);   // wlo = wh[2l], whi = wh[(2l-1)&63]
}

__device__ __forceinline__ float rbm_fe_from(const u64 P[4], u64 v,
                                             const float* __restrict__ csh,
                                             float bsc) {
    float a0, a1, a2, a3, b0, b1, b2, b3;
    rbm_unpack2(P[0], a0, a1);
    rbm_unpack2(P[1], a2, a3);
    rbm_unpack2(P[2], b0, b1);
    rbm_unpack2(P[3], b2, b3);
    float s = rbm_softplus(a0 + csh[0]) + rbm_softplus(b0 + csh[0])
            + rbm_softplus(a1 + csh[1]) + rbm_softplus(b1 + csh[1])
            + rbm_softplus(a2 + csh[2]) + rbm_softplus(b2 + csh[2])
            + rbm_softplus(a3 + csh[3]) + rbm_softplus(b3 + csh[3]);
    s = rbm_warp_sum(s);
    return -bsc * (float)__popcll(v) - s;
}

// ---------------------------------------------------------------------------
// Main kernel: one warp per sample pair (b, b+32768); 8 warps/block,
// 2 blocks/SM (96 KB smem each).
// ---------------------------------------------------------------------------
__global__ void __launch_bounds__(TPB, 2)
rbm_gibbs_kernel(float* __restrict__ out,
                 const float* __restrict__ v_data,
                 const float* __restrict__ b_scalar,
                 const float* __restrict__ c_vector,
                 RbmKeys keys) {
    extern __shared__ char smem_dyn[];
    ulonglong2* Tf = (ulonglong2*)smem_dyn;
    u64*        Tq = (u64*)(smem_dyn + SMEM_TF_BYTES);
    __shared__ float  csh[4];
    __shared__ double wsum[WPB];

    const int tid  = threadIdx.x;
    const int lane = tid & 31;
    const int wid  = tid >> 5;

    {   // copy LUTs from global (L2-resident) to shared
        float4* sf = (float4*)smem_dyn;
        for (int i = tid; i < 32 * 64; i += TPB) sf[i] = gTf[i];
        float4* sq = (float4*)(smem_dyn + SMEM_TF_BYTES);
        for (int i = tid; i < 4096; i += TPB) sq[i] = gTq[i];
    }
    if (tid < 4) csh[tid] = c_vector[tid];
    __syncthreads();

    const float bsc = b_scalar[0];
    const float nb  = bsc * NEG_L2E;
    float nca[4];
    #pragma unroll
    for (int a = 0; a < 4; a++) nca[a] = csh[a] * NEG_L2E;

    const int w  = blockIdx.x * WPB + wid;
    const int b0 = w;
    const int b1 = w + PAIRS;

    // Load v_data as bitmasks
    u64 v0, v1;
    {
        float a0 = v_data[(size_t)b0 * 64 + lane];
        float a1 = v_data[(size_t)b0 * 64 + lane + 32];
        unsigned lo = __ballot_sync(0xffffffffu, a0 != 0.0f);
        unsigned hi = __ballot_sync(0xffffffffu, a1 != 0.0f);
        v0 = (u64)lo | ((u64)hi << 32);
        float c0 = v_data[(size_t)b1 * 64 + lane];
        float c1 = v_data[(size_t)b1 * 64 + lane + 32];
        lo = __ballot_sync(0xffffffffu, c0 != 0.0f);
        hi = __ballot_sync(0xffffffffu, c1 != 0.0f);
        v1 = (u64)lo | ((u64)hi << 32);
    }

    // Hoisted: wv of initial state, shared by fe_data and Gibbs step 0
    u64 P0[4], P1[4];
    rbm_wv32(v0, lane, Tf, P0);
    rbm_wv32(v1, lane, Tf, P1);
    const float fed0 = rbm_fe_from(P0, v0, csh, bsc);
    const float fed1 = rbm_fe_from(P1, v1, csh, bsc);

    const unsigned baseH = (unsigned)b0 * 256u;
    const unsigned baseV = (unsigned)b0 * 64u + (unsigned)lane;

    #pragma unroll 1
    for (int t = 0; t < GIBBS_K; t++) {
        if (t) {
            rbm_wv32(v0, lane, Tf, P0);
            rbm_wv32(v1, lane, Tf, P1);
        }

        // e = exp(-(wv + c)); layout e[s][a*2+ii]
        float e0[8], e1[8];
        {
            float x, y;
            rbm_unpack2(P0[0], x, y); e0[0] = rbm_nexp(x, nca[0]); e0[2] = rbm_nexp(y, nca[1]);
            rbm_unpack2(P0[1], x, y); e0[4] = rbm_nexp(x, nca[2]); e0[6] = rbm_nexp(y, nca[3]);
            rbm_unpack2(P0[2], x, y); e0[1] = rbm_nexp(x, nca[0]); e0[3] = rbm_nexp(y, nca[1]);
            rbm_unpack2(P0[3], x, y); e0[5] = rbm_nexp(x, nca[2]); e0[7] = rbm_nexp(y, nca[3]);
            rbm_unpack2(P1[0], x, y); e1[0] = rbm_nexp(x, nca[0]); e1[2] = rbm_nexp(y, nca[1]);
            rbm_unpack2(P1[1], x, y); e1[4] = rbm_nexp(x, nca[2]); e1[6] = rbm_nexp(y, nca[3]);
            rbm_unpack2(P1[2], x, y); e1[1] = rbm_nexp(x, nca[0]); e1[3] = rbm_nexp(y, nca[1]);
            rbm_unpack2(P1[3], x, y); e1[5] = rbm_nexp(x, nca[2]); e1[7] = rbm_nexp(y, nca[3]);
        }

        const uint2 kh = keys.kh[t];
        u64 h0[4], h1[4];
        #pragma unroll
        for (int a = 0; a < 4; a++) {
            unsigned cA = baseH + (unsigned)(a * 64 + lane);
            unsigned cB = cA + 32u;
            unsigned rA0, rA1, rB0, rB1;
            rbm_tf2x32(kh.x, kh.y, cA, cA + HALF_H, rA0, rA1);
            rbm_tf2x32(kh.x, kh.y, cB, cB + HALF_H, rB0, rB1);
            unsigned l0 = __ballot_sync(0xffffffffu, rbm_draw(rA0, e0[a * 2 + 0]));
            unsigned g0 = __ballot_sync(0xffffffffu, rbm_draw(rB0, e0[a * 2 + 1]));
            unsigned l1 = __ballot_sync(0xffffffffu, rbm_draw(rA1, e1[a * 2 + 0]));
            unsigned g1 = __ballot_sync(0xffffffffu, rbm_draw(rB1, e1[a * 2 + 1]));
            h0[a] = (u64)l0 | ((u64)g0 << 32);
            h1[a] = (u64)l1 | ((u64)g1 << 32);
        }

        // wh packed at outputs (2l, 2l-1), then remap to (lane, lane+32)
        float w0lo, w0hi, w1lo, w1hi;
        rbm_wh64(h0, lane, Tq, w0lo, w0hi);
        rbm_wh64(h1, lane, Tq, w1lo, w1hi);

        const int src  = (lane + 1) >> 1;
        const int src2 = src + 16;          // shfl wraps mod 32
        float s0 = __shfl_sync(0xffffffffu, w0lo, src);
        float t0 = __shfl_sync(0xffffffffu, w0hi, src);
        float s1 = __shfl_sync(0xffffffffu, w0lo, src2);
        float t1 = __shfl_sync(0xffffffffu, w0hi, src2);
        float u0 = __shfl_sync(0xffffffffu, w1lo, src);
        float q0 = __shfl_sync(0xffffffffu, w1hi, src);
        float u1 = __shfl_sync(0xffffffffu, w1lo, src2);
        float q1 = __shfl_sync(0xffffffffu, w1hi, src2);
        const bool odd = (lane & 1);
        float wh00 = odd ? t0 : s0;   // sample0, i=lane
        float wh01 = odd ? t1 : s1;   // sample0, i=lane+32
        float wh10 = odd ? q0 : u0;   // sample1, i=lane
        float wh11 = odd ? q1 : u1;   // sample1, i=lane+32

        float ev00 = rbm_nexp(wh00, nb);
        float ev01 = rbm_nexp(wh01, nb);
        float ev10 = rbm_nexp(wh10, nb);
        float ev11 = rbm_nexp(wh11, nb);

        const uint2 kv = keys.kv[t];
        unsigned r00, r01, r10, r11;
        rbm_tf2x32(kv.x, kv.y, baseV,       baseV + HALF_V,       r00, r01);
        rbm_tf2x32(kv.x, kv.y, baseV + 32u, baseV + 32u + HALF_V, r10, r11);
        unsigned m0l = __ballot_sync(0xffffffffu, rbm_draw(r00, ev00));
        unsigned m0h = __ballot_sync(0xffffffffu, rbm_draw(r10, ev01));
        unsigned m1l = __ballot_sync(0xffffffffu, rbm_draw(r01, ev10));
        unsigned m1h = __ballot_sync(0xffffffffu, rbm_draw(r11, ev11));
        v0 = (u64)m0l | ((u64)m0h << 32);
        v1 = (u64)m1l | ((u64)m1h << 32);
    }

    rbm_wv32(v0, lane, Tf, P0);
    rbm_wv32(v1, lane, Tf, P1);
    const float fem0 = rbm_fe_from(P0, v0, csh, bsc);
    const float fem1 = rbm_fe_from(P1, v1, csh, bsc);
    const float diff = (fed0 - fem0) + (fed1 - fem1);

    if (lane == 0) wsum[wid] = (double)diff;
    __syncthreads();
    if (tid == 0) {
        double s = 0.0;
        #pragma unroll
        for (int i = 0; i < WPB; i++) s += wsum[i];
        atomicAdd(&g_rbm_sum, s);
        __threadfence();
        unsigned ticket = atomicAdd(&g_rbm_cnt, 1u);
        if (ticket == NBLOCKS - 1) {
            __threadfence();
            double total = atomicAdd(&g_rbm_sum, 0.0);
            out[0] = (float)(total / (double)BATCH);
            g_rbm_sum = 0.0;        // reset for next graph replay
            g_rbm_cnt = 0u;
        }
    }
}

// ---------------------------------------------------------------------------
// Host: replicate scan key-split chain: key(42); per step k,kh,kv = split(k,3)
// ---------------------------------------------------------------------------
extern "C" void kernel_launch(void* const* d_in, const int* in_sizes, int n_in,
                              void* d_out, int out_size) {
    const float* v_data   = (const float*)d_in[0];
    const float* kern     = (const float*)d_in[1];
    const float* b_scalar = (const float*)d_in[2];
    const float* c_vector = (const float*)d_in[3];

    RbmKeys keys;
    unsigned k0 = 0u, k1 = 42u;
    for (int t = 0; t < GIBBS_K; t++) {
        unsigned A0, B0, A1, B1, A2, B2;
        rbm_tf2x32(k0, k1, 0u, 3u, A0, B0);
        rbm_tf2x32(k0, k1, 1u, 4u, A1, B1);
        rbm_tf2x32(k0, k1, 2u, 5u, A2, B2);
        keys.kh[t] = make_uint2(A2, B0);  // keys[1]
        keys.kv[t] = make_uint2(B1, B2);  // keys[2]
        k0 = A0; k1 = A1;                 // carried key
    }

    cudaFuncSetAttribute(rbm_gibbs_kernel,
                         cudaFuncAttributeMaxDynamicSharedMemorySize, SMEM_BYTES);

    rbm_build_tables<<<1, 256>>>(kern);
    rbm_gibbs_kernel<<<NBLOCKS, TPB, SMEM_BYTES>>>((float*)d_out, v_data,
                                                   b_scalar, c_vector, keys);
}

// round 14
// speedup vs baseline: 1.0399x; 1.0149x over previous
#include <cuda_runtime.h>
#include <cstdint>

#define GIBBS_K   10
#define BATCH     65536
#define PAIRS     32768          // BATCH/2 : warp handles (b, b+PAIRS)
#define WPB       8
#define TPB       (WPB*32)       // 256
#define NBLOCKS   (PAIRS/WPB)    // 4096

#define HALF_H 8388608u          // (BATCH*ALPHA*N)/2
#define HALF_V 2097152u          // (BATCH*N)/2

#define SMEM_TF_BYTES 32768      // wv radix-32 table: 32n x 64o x float4
#define SMEM_TQ_BYTES 65536      // wh radix-64 pair table: 4a x 64n x 32p x float2
#define SMEM_BYTES    (SMEM_TF_BYTES + SMEM_TQ_BYTES)

#define NEG_L2E (-1.4426950408889634f)

typedef unsigned long long u64;

// Expanded keys: ks2 = k0 ^ k1 ^ 0x1BD11BDA precomputed on host per step.
struct RbmKeys {
    uint2    kh[GIBBS_K];
    unsigned khs[GIBBS_K];
    uint2    kv[GIBBS_K];
    unsigned kvs[GIBBS_K];
};

__device__ double   g_rbm_sum = 0.0;
__device__ unsigned g_rbm_cnt = 0u;
__device__ float4   gTf[32 * 64];   // wv: [n][o] -> {a0,a1,a2,a3}
__device__ float4   gTq[4096];      // wh: pairs of float2 entries

// ---------------- JAX threefry2x32 (exact) ----------------
__host__ __device__ __forceinline__ unsigned rbm_rotl32(unsigned x, int r) {
#ifdef __CUDA_ARCH__
    return __funnelshift_l(x, x, r);
#else
    return (x << r) | (x >> (32 - r));
#endif
}

// Device version takes precomputed ks2.
__device__ __forceinline__ void rbm_tf2x32k(unsigned k0, unsigned k1, unsigned ks2,
                                            unsigned x0, unsigned x1,
                                            unsigned& o0, unsigned& o1) {
    x0 += k0; x1 += k1;
#define TFR(r) { x0 += x1; x1 = rbm_rotl32(x1, r); x1 ^= x0; }
    TFR(13) TFR(15) TFR(26) TFR(6)
    x0 += k1;  x1 += ks2 + 1u;
    TFR(17) TFR(29) TFR(16) TFR(24)
    x0 += ks2; x1 += k0 + 2u;
    TFR(13) TFR(15) TFR(26) TFR(6)
    x0 += k0;  x1 += k1 + 3u;
    TFR(17) TFR(29) TFR(16) TFR(24)
    x0 += k1;  x1 += ks2 + 4u;
    TFR(13) TFR(15) TFR(26) TFR(6)
    x0 += ks2; x1 += k0 + 5u;
#undef TFR
    o0 = x0; o1 = x1;
}

__host__ void rbm_tf2x32_host(unsigned k0, unsigned k1,
                              unsigned x0, unsigned x1,
                              unsigned& o0, unsigned& o1) {
    unsigned ks2 = k0 ^ k1 ^ 0x1BD11BDAu;
    x0 += k0; x1 += k1;
#define TFR(r) { x0 += x1; x1 = (x1 << r) | (x1 >> (32 - r)); x1 ^= x0; }
    TFR(13) TFR(15) TFR(26) TFR(6)
    x0 += k1;  x1 += ks2 + 1u;
    TFR(17) TFR(29) TFR(16) TFR(24)
    x0 += ks2; x1 += k0 + 2u;
    TFR(13) TFR(15) TFR(26) TFR(6)
    x0 += k0;  x1 += k1 + 3u;
    TFR(17) TFR(29) TFR(16) TFR(24)
    x0 += k1;  x1 += ks2 + 4u;
    TFR(13) TFR(15) TFR(26) TFR(6)
    x0 += ks2; x1 += k0 + 5u;
#undef TFR
    o0 = x0; o1 = x1;
}

// jax.random.uniform f32, FMA-pipe form:
// m = b>>9 via umulhi (IMAD.HI), OR via integer add (exact: m < 2^23).
__device__ __forceinline__ float rbm_u01(unsigned b) {
    unsigned m = __umulhi(b, 0x00800000u);          // b >> 9
    return __uint_as_float(m + 0x3f800000u) - 1.0f;
}

__device__ __forceinline__ float rbm_softplus(float x) {
    return fmaxf(x, 0.0f) + log1pf(expf(-fabsf(x)));
}
__device__ __forceinline__ float rbm_warp_sum(float v) {
    #pragma unroll
    for (int s = 16; s > 0; s >>= 1) v += __shfl_xor_sync(0xffffffffu, v, s);
    return v;
}
__device__ __forceinline__ void rbm_unpack2(u64 p, float& lo, float& hi) {
    asm("mov.b64 {%0, %1}, %2;" : "=f"(lo), "=f"(hi) : "l"(p));
}
__device__ __forceinline__ u64 rbm_addx2(u64 a, u64 b) {
    u64 r; asm("add.rn.f32x2 %0, %1, %2;" : "=l"(r) : "l"(a), "l"(b)); return r;
}
__device__ __forceinline__ float rbm_ex2(float x) {
    float r; asm("ex2.approx.f32 %0, %1;" : "=f"(r) : "f"(x)); return r;
}
// e = exp(-(x + c)) = ex2(fma(x, -log2e, nc)), nc = -c*log2e precomputed
__device__ __forceinline__ float rbm_nexp(float x, float nc) {
    return rbm_ex2(fmaf(x, NEG_L2E, nc));
}
// Bernoulli: u < 1/(1+e)  <=>  fma(u, e, u) < 1
__device__ __forceinline__ bool rbm_draw(unsigned bits, float e) {
    float u = rbm_u01(bits);
    return fmaf(u, e, u) < 1.0f;
}

// ---------------------------------------------------------------------------
// Pre-kernel: build LUTs once (1 block).
// gTf[n*64+o].a = sum_{t<5} bit_t(n) * K[a][(o+t)&63]          (radix-32 wv)
// gTq entry (a,n,p) float2:                                     (radix-64 wh)
//   e0 = sum_{t<6} bit_t(n) * K[a][(2p-1-t)&63]   (output i=2p)
//   e1 = sum_{t<6} bit_t(n) * K[a][(2p-2-t)&63]   (output i=2p-1)
// ---------------------------------------------------------------------------
__global__ void rbm_build_tables(const float* __restrict__ kern) {
    const int tid = threadIdx.x;
    for (int idx = tid; idx < 32 * 64; idx += 256) {
        int o = idx & 63, n = idx >> 6;
        float4 s = make_float4(0.f, 0.f, 0.f, 0.f);
        #pragma unroll
        for (int t = 0; t < 5; t++) {
            if ((n >> t) & 1) {
                int j = (o + t) & 63;
                s.x += kern[j];
                s.y += kern[64 + j];
                s.z += kern[128 + j];
                s.w += kern[192 + j];
            }
        }
        gTf[idx] = s;
    }
    for (int idx2 = tid; idx2 < 4096; idx2 += 256) {
        int a = idx2 >> 10, n = (idx2 >> 4) & 63, p0 = (idx2 & 15) * 2;
        float4 r = make_float4(0.f, 0.f, 0.f, 0.f);
        #pragma unroll
        for (int t = 0; t < 6; t++) {
            if ((n >> t) & 1) {
                r.x += kern[a * 64 + ((2 * p0 - 1 - t + 128) & 63)];
                r.y += kern[a * 64 + ((2 * p0 - 2 - t + 128) & 63)];
                r.z += kern[a * 64 + ((2 * p0 + 1 - t + 128) & 63)];
                r.w += kern[a * 64 + ((2 * p0 - t + 128) & 63)];
            }
        }
        gTq[idx2] = r;
    }
}

// ---------------------------------------------------------------------------
// wv radix-32: 13 chunks of 5 bits.
// P[0]=(a0,a1)@i0  P[1]=(a2,a3)@i0  P[2]=(a0,a1)@i1  P[3]=(a2,a3)@i1
// ---------------------------------------------------------------------------
__device__ __forceinline__ void rbm_wv32(u64 v, int lane,
                                         const ulonglong2* __restrict__ Tf,
                                         u64 P[4]) {
    P[0] = 0ull; P[1] = 0ull; P[2] = 0ull; P[3] = 0ull;
    int off = (-lane) & 63;
    #pragma unroll
    for (int c = 0; c < 13; c++) {
        unsigned n = (unsigned)(v >> (5 * c)) & 31u;
        int idx = (int)n * 64 + off;
        ulonglong2 A = Tf[idx];
        ulonglong2 B = Tf[idx ^ 32];
        P[0] = rbm_addx2(P[0], A.x);
        P[1] = rbm_addx2(P[1], A.y);
        P[2] = rbm_addx2(P[2], B.x);
        P[3] = rbm_addx2(P[3], B.y);
        off = (off + 5) & 63;
    }
}

// ---------------------------------------------------------------------------
// wh radix-64: 11 chunks of 6 bits per alpha; lane l accumulates packed
// outputs (2l, (2l-1)&63); table index p' = (l - 3c) & 31.
// SINGLE accumulator (R8 codegen: one address chain + immediate offsets).
// ---------------------------------------------------------------------------
__device__ __forceinline__ void rbm_wh64(const u64 h[4], int lane,
                                         const u64* __restrict__ Tq,
                                         float& wlo, float& whi) {
    u64 Q = 0ull;
    int p = lane;
    #pragma unroll
    for (int c = 0; c < 11; c++) {
        #pragma unroll
        for (int a = 0; a < 4; a++) {
            unsigned n = (unsigned)(h[a] >> (6 * c)) & 63u;
            Q = rbm_addx2(Q, Tq[(a * 64 + (int)n) * 32 + p]);
        }
        p = (p + 29) & 31;   // -3 mod 32
    }
    rbm_unpack2(Q, wlo, whi);   // wlo = wh[2l], whi = wh[(2l-1)&63]
}

__device__ __forceinline__ float rbm_fe_from(const u64 P[4], u64 v,
                                             const float* __restrict__ csh,
                                             float bsc) {
    float a0, a1, a2, a3, b0, b1, b2, b3;
    rbm_unpack2(P[0], a0, a1);
    rbm_unpack2(P[1], a2, a3);
    rbm_unpack2(P[2], b0, b1);
    rbm_unpack2(P[3], b2, b3);
    float s = rbm_softplus(a0 + csh[0]) + rbm_softplus(b0 + csh[0])
            + rbm_softplus(a1 + csh[1]) + rbm_softplus(b1 + csh[1])
            + rbm_softplus(a2 + csh[2]) + rbm_softplus(b2 + csh[2])
            + rbm_softplus(a3 + csh[3]) + rbm_softplus(b3 + csh[3]);
    s = rbm_warp_sum(s);
    return -bsc * (float)__popcll(v) - s;
}

// ---------------------------------------------------------------------------
// Main kernel: one warp per sample pair (b, b+32768); 8 warps/block,
// 2 blocks/SM (96 KB smem each).
// ---------------------------------------------------------------------------
__global__ void __launch_bounds__(TPB, 2)
rbm_gibbs_kernel(float* __restrict__ out,
                 const float* __restrict__ v_data,
                 const float* __restrict__ b_scalar,
                 const float* __restrict__ c_vector,
                 RbmKeys keys) {
    extern __shared__ char smem_dyn[];
    ulonglong2* Tf = (ulonglong2*)smem_dyn;
    u64*        Tq = (u64*)(smem_dyn + SMEM_TF_BYTES);
    __shared__ float  csh[4];
    __shared__ double wsum[WPB];

    const int tid  = threadIdx.x;
    const int lane = tid & 31;
    const int wid  = tid >> 5;

    {   // copy LUTs from global (L2-resident) to shared
        float4* sf = (float4*)smem_dyn;
        for (int i = tid; i < 32 * 64; i += TPB) sf[i] = gTf[i];
        float4* sq = (float4*)(smem_dyn + SMEM_TF_BYTES);
        for (int i = tid; i < 4096; i += TPB) sq[i] = gTq[i];
    }
    if (tid < 4) csh[tid] = c_vector[tid];
    __syncthreads();

    const float bsc = b_scalar[0];
    const float nb  = bsc * NEG_L2E;
    float nca[4];
    #pragma unroll
    for (int a = 0; a < 4; a++) nca[a] = csh[a] * NEG_L2E;

    const int w  = blockIdx.x * WPB + wid;
    const int b0 = w;
    const int b1 = w + PAIRS;

    // Load v_data as bitmasks
    u64 v0, v1;
    {
        float a0 = v_data[(size_t)b0 * 64 + lane];
        float a1 = v_data[(size_t)b0 * 64 + lane + 32];
        unsigned lo = __ballot_sync(0xffffffffu, a0 != 0.0f);
        unsigned hi = __ballot_sync(0xffffffffu, a1 != 0.0f);
        v0 = (u64)lo | ((u64)hi << 32);
        float c0 = v_data[(size_t)b1 * 64 + lane];
        float c1 = v_data[(size_t)b1 * 64 + lane + 32];
        lo = __ballot_sync(0xffffffffu, c0 != 0.0f);
        hi = __ballot_sync(0xffffffffu, c1 != 0.0f);
        v1 = (u64)lo | ((u64)hi << 32);
    }

    // Hoisted: wv of initial state, shared by fe_data and Gibbs step 0
    u64 P0[4], P1[4];
    rbm_wv32(v0, lane, Tf, P0);
    rbm_wv32(v1, lane, Tf, P1);
    const float fed0 = rbm_fe_from(P0, v0, csh, bsc);
    const float fed1 = rbm_fe_from(P1, v1, csh, bsc);

    const unsigned baseH = (unsigned)b0 * 256u;
    const unsigned baseV = (unsigned)b0 * 64u + (unsigned)lane;

    #pragma unroll 1
    for (int t = 0; t < GIBBS_K; t++) {
        if (t) {
            rbm_wv32(v0, lane, Tf, P0);
            rbm_wv32(v1, lane, Tf, P1);
        }

        // e = exp(-(wv + c)); layout e[s][a*2+ii]
        float e0[8], e1[8];
        {
            float x, y;
            rbm_unpack2(P0[0], x, y); e0[0] = rbm_nexp(x, nca[0]); e0[2] = rbm_nexp(y, nca[1]);
            rbm_unpack2(P0[1], x, y); e0[4] = rbm_nexp(x, nca[2]); e0[6] = rbm_nexp(y, nca[3]);
            rbm_unpack2(P0[2], x, y); e0[1] = rbm_nexp(x, nca[0]); e0[3] = rbm_nexp(y, nca[1]);
            rbm_unpack2(P0[3], x, y); e0[5] = rbm_nexp(x, nca[2]); e0[7] = rbm_nexp(y, nca[3]);
            rbm_unpack2(P1[0], x, y); e1[0] = rbm_nexp(x, nca[0]); e1[2] = rbm_nexp(y, nca[1]);
            rbm_unpack2(P1[1], x, y); e1[4] = rbm_nexp(x, nca[2]); e1[6] = rbm_nexp(y, nca[3]);
            rbm_unpack2(P1[2], x, y); e1[1] = rbm_nexp(x, nca[0]); e1[3] = rbm_nexp(y, nca[1]);
            rbm_unpack2(P1[3], x, y); e1[5] = rbm_nexp(x, nca[2]); e1[7] = rbm_nexp(y, nca[3]);
        }

        const uint2 kh = keys.kh[t];
        const unsigned khs = keys.khs[t];
        u64 h0[4], h1[4];
        #pragma unroll
        for (int a = 0; a < 4; a++) {
            unsigned cA = baseH + (unsigned)(a * 64 + lane);
            unsigned cB = cA + 32u;
            unsigned rA0, rA1, rB0, rB1;
            rbm_tf2x32k(kh.x, kh.y, khs, cA, cA + HALF_H, rA0, rA1);
            rbm_tf2x32k(kh.x, kh.y, khs, cB, cB + HALF_H, rB0, rB1);
            unsigned l0 = __ballot_sync(0xffffffffu, rbm_draw(rA0, e0[a * 2 + 0]));
            unsigned g0 = __ballot_sync(0xffffffffu, rbm_draw(rB0, e0[a * 2 + 1]));
            unsigned l1 = __ballot_sync(0xffffffffu, rbm_draw(rA1, e1[a * 2 + 0]));
            unsigned g1 = __ballot_sync(0xffffffffu, rbm_draw(rB1, e1[a * 2 + 1]));
            h0[a] = (u64)l0 | ((u64)g0 << 32);
            h1[a] = (u64)l1 | ((u64)g1 << 32);
        }

        // wh packed at outputs (2l, 2l-1), then remap to (lane, lane+32)
        float w0lo, w0hi, w1lo, w1hi;
        rbm_wh64(h0, lane, Tq, w0lo, w0hi);
        rbm_wh64(h1, lane, Tq, w1lo, w1hi);

        const int src  = (lane + 1) >> 1;
        const int src2 = src + 16;          // shfl wraps mod 32
        float s0 = __shfl_sync(0xffffffffu, w0lo, src);
        float t0 = __shfl_sync(0xffffffffu, w0hi, src);
        float s1 = __shfl_sync(0xffffffffu, w0lo, src2);
        float t1 = __shfl_sync(0xffffffffu, w0hi, src2);
        float u0 = __shfl_sync(0xffffffffu, w1lo, src);
        float q0 = __shfl_sync(0xffffffffu, w1hi, src);
        float u1 = __shfl_sync(0xffffffffu, w1lo, src2);
        float q1 = __shfl_sync(0xffffffffu, w1hi, src2);
        const bool odd = (lane & 1);
        float wh00 = odd ? t0 : s0;   // sample0, i=lane
        float wh01 = odd ? t1 : s1;   // sample0, i=lane+32
        float wh10 = odd ? q0 : u0;   // sample1, i=lane
        float wh11 = odd ? q1 : u1;   // sample1, i=lane+32

        float ev00 = rbm_nexp(wh00, nb);
        float ev01 = rbm_nexp(wh01, nb);
        float ev10 = rbm_nexp(wh10, nb);
        float ev11 = rbm_nexp(wh11, nb);

        const uint2 kv = keys.kv[t];
        const unsigned kvs = keys.kvs[t];
        unsigned r00, r01, r10, r11;
        rbm_tf2x32k(kv.x, kv.y, kvs, baseV,       baseV + HALF_V,       r00, r01);
        rbm_tf2x32k(kv.x, kv.y, kvs, baseV + 32u, baseV + 32u + HALF_V, r10, r11);
        unsigned m0l = __ballot_sync(0xffffffffu, rbm_draw(r00, ev00));
        unsigned m0h = __ballot_sync(0xffffffffu, rbm_draw(r10, ev01));
        unsigned m1l = __ballot_sync(0xffffffffu, rbm_draw(r01, ev10));
        unsigned m1h = __ballot_sync(0xffffffffu, rbm_draw(r11, ev11));
        v0 = (u64)m0l | ((u64)m0h << 32);
        v1 = (u64)m1l | ((u64)m1h << 32);
    }

    rbm_wv32(v0, lane, Tf, P0);
    rbm_wv32(v1, lane, Tf, P1);
    const float fem0 = rbm_fe_from(P0, v0, csh, bsc);
    const float fem1 = rbm_fe_from(P1, v1, csh, bsc);
    const float diff = (fed0 - fem0) + (fed1 - fem1);

    if (lane == 0) wsum[wid] = (double)diff;
    __syncthreads();
    if (tid == 0) {
        double s = 0.0;
        #pragma unroll
        for (int i = 0; i < WPB; i++) s += wsum[i];
        atomicAdd(&g_rbm_sum, s);
        __threadfence();
        unsigned ticket = atomicAdd(&g_rbm_cnt, 1u);
        if (ticket == NBLOCKS - 1) {
            __threadfence();
            double total = atomicAdd(&g_rbm_sum, 0.0);
            out[0] = (float)(total / (double)BATCH);
            g_rbm_sum = 0.0;        // reset for next graph replay
            g_rbm_cnt = 0u;
        }
    }
}

// ---------------------------------------------------------------------------
// Host: replicate scan key-split chain: key(42); per step k,kh,kv = split(k,3)
// ---------------------------------------------------------------------------
extern "C" void kernel_launch(void* const* d_in, const int* in_sizes, int n_in,
                              void* d_out, int out_size) {
    const float* v_data   = (const float*)d_in[0];
    const float* kern     = (const float*)d_in[1];
    const float* b_scalar = (const float*)d_in[2];
    const float* c_vector = (const float*)d_in[3];

    RbmKeys keys;
    unsigned k0 = 0u, k1 = 42u;
    for (int t = 0; t < GIBBS_K; t++) {
        unsigned A0, B0, A1, B1, A2, B2;
        rbm_tf2x32_host(k0, k1, 0u, 3u, A0, B0);
        rbm_tf2x32_host(k0, k1, 1u, 4u, A1, B1);
        rbm_tf2x32_host(k0, k1, 2u, 5u, A2, B2);
        keys.kh[t]  = make_uint2(A2, B0);  // keys[1]
        keys.khs[t] = A2 ^ B0 ^ 0x1BD11BDAu;
        keys.kv[t]  = make_uint2(B1, B2);  // keys[2]
        keys.kvs[t] = B1 ^ B2 ^ 0x1BD11BDAu;
        k0 = A0; k1 = A1;                  // carried key
    }

    cudaFuncSetAttribute(rbm_gibbs_kernel,
                         cudaFuncAttributeMaxDynamicSharedMemorySize, SMEM_BYTES);

    rbm_build_tables<<<1, 256>>>(kern);
    rbm_gibbs_kernel<<<NBLOCKS, TPB, SMEM_BYTES>>>((float*)d_out, v_data,
                                                   b_scalar, c_vector, keys);
}

// round 15
// speedup vs baseline: 1.0807x; 1.0393x over previous
#include <cuda_runtime.h>
#include <cstdint>

#define GIBBS_K   10
#define BATCH     65536
#define PAIRS     32768          // BATCH/2 : warp handles (b, b+PAIRS)
#define WPB       8
#define TPB       (WPB*32)       // 256
#define NBLOCKS   (PAIRS/WPB)    // 4096

#define HALF_H 8388608u          // (BATCH*ALPHA*N)/2
#define HALF_V 2097152u          // (BATCH*N)/2

#define SMEM_TF_BYTES 32768      // wv radix-32 table: 32n x 64o x float4
#define SMEM_TQ_BYTES 65536      // wh radix-64 pair table: 4a x 64n x 32p x float2
#define SMEM_BYTES    (SMEM_TF_BYTES + SMEM_TQ_BYTES)

typedef unsigned long long u64;

// Expanded keys: ks2 = k0 ^ k1 ^ 0x1BD11BDA precomputed on host per step.
struct RbmKeys {
    uint2    kh[GIBBS_K];
    unsigned khs[GIBBS_K];
    uint2    kv[GIBBS_K];
    unsigned kvs[GIBBS_K];
};

__device__ double   g_rbm_sum = 0.0;
__device__ unsigned g_rbm_cnt = 0u;
__device__ float4   gTf[32 * 64];   // wv: [n][o] -> {a0,a1,a2,a3}
__device__ float4   gTq[4096];      // wh: pairs of float2 entries

// ---------------- JAX threefry2x32 (exact) ----------------
__host__ __device__ __forceinline__ unsigned rbm_rotl32(unsigned x, int r) {
#ifdef __CUDA_ARCH__
    return __funnelshift_l(x, x, r);
#else
    return (x << r) | (x >> (32 - r));
#endif
}

// Device version takes precomputed ks2 (saves 2 LOP3 per call).
__device__ __forceinline__ void rbm_tf2x32k(unsigned k0, unsigned k1, unsigned ks2,
                                            unsigned x0, unsigned x1,
                                            unsigned& o0, unsigned& o1) {
    x0 += k0; x1 += k1;
#define TFR(r) { x0 += x1; x1 = rbm_rotl32(x1, r); x1 ^= x0; }
    TFR(13) TFR(15) TFR(26) TFR(6)
    x0 += k1;  x1 += ks2 + 1u;
    TFR(17) TFR(29) TFR(16) TFR(24)
    x0 += ks2; x1 += k0 + 2u;
    TFR(13) TFR(15) TFR(26) TFR(6)
    x0 += k0;  x1 += k1 + 3u;
    TFR(17) TFR(29) TFR(16) TFR(24)
    x0 += k1;  x1 += ks2 + 4u;
    TFR(13) TFR(15) TFR(26) TFR(6)
    x0 += ks2; x1 += k0 + 5u;
#undef TFR
    o0 = x0; o1 = x1;
}

__host__ void rbm_tf2x32_host(unsigned k0, unsigned k1,
                              unsigned x0, unsigned x1,
                              unsigned& o0, unsigned& o1) {
    unsigned ks2 = k0 ^ k1 ^ 0x1BD11BDAu;
    x0 += k0; x1 += k1;
#define TFR(r) { x0 += x1; x1 = (x1 << r) | (x1 >> (32 - r)); x1 ^= x0; }
    TFR(13) TFR(15) TFR(26) TFR(6)
    x0 += k1;  x1 += ks2 + 1u;
    TFR(17) TFR(29) TFR(16) TFR(24)
    x0 += ks2; x1 += k0 + 2u;
    TFR(13) TFR(15) TFR(26) TFR(6)
    x0 += k0;  x1 += k1 + 3u;
    TFR(17) TFR(29) TFR(16) TFR(24)
    x0 += k1;  x1 += ks2 + 4u;
    TFR(13) TFR(15) TFR(26) TFR(6)
    x0 += ks2; x1 += k0 + 5u;
#undef TFR
    o0 = x0; o1 = x1;
}

// jax.random.uniform f32: bitwise-identical FMA-pipe form.
// m = b>>9 via umulhi (IMAD.HI); OR via integer add (exact: m < 2^23).
__device__ __forceinline__ float rbm_u01(unsigned b) {
    unsigned m = __umulhi(b, 0x00800000u);          // b >> 9
    return __uint_as_float(m + 0x3f800000u) - 1.0f;
}

// jnp.logaddexp(x,0)
__device__ __forceinline__ float rbm_softplus(float x) {
    return fmaxf(x, 0.0f) + log1pf(expf(-fabsf(x)));
}
__device__ __forceinline__ float rbm_warp_sum(float v) {
    #pragma unroll
    for (int s = 16; s > 0; s >>= 1) v += __shfl_xor_sync(0xffffffffu, v, s);
    return v;
}
__device__ __forceinline__ void rbm_unpack2(u64 p, float& lo, float& hi) {
    asm("mov.b64 {%0, %1}, %2;" : "=f"(lo), "=f"(hi) : "l"(p));
}
__device__ __forceinline__ u64 rbm_addx2(u64 a, u64 b) {
    u64 r; asm("add.rn.f32x2 %0, %1, %2;" : "=l"(r) : "l"(a), "l"(b)); return r;
}
// Bernoulli: u < 1/(1+e)  <=>  fma(u, e, u) < 1,  e = exp(-x)
__device__ __forceinline__ bool rbm_draw(unsigned bits, float e) {
    float u = rbm_u01(bits);
    return fmaf(u, e, u) < 1.0f;
}

// ---------------------------------------------------------------------------
// Pre-kernel: build LUTs once (1 block).
// gTf[n*64+o].a = sum_{t<5} bit_t(n) * K[a][(o+t)&63]          (radix-32 wv)
// gTq entry (a,n,p) float2:                                     (radix-64 wh)
//   e0 = sum_{t<6} bit_t(n) * K[a][(2p-1-t)&63]   (output i=2p)
//   e1 = sum_{t<6} bit_t(n) * K[a][(2p-2-t)&63]   (output i=2p-1)
// ---------------------------------------------------------------------------
__global__ void rbm_build_tables(const float* __restrict__ kern) {
    const int tid = threadIdx.x;
    for (int idx = tid; idx < 32 * 64; idx += 256) {
        int o = idx & 63, n = idx >> 6;
        float4 s = make_float4(0.f, 0.f, 0.f, 0.f);
        #pragma unroll
        for (int t = 0; t < 5; t++) {
            if ((n >> t) & 1) {
                int j = (o + t) & 63;
                s.x += kern[j];
                s.y += kern[64 + j];
                s.z += kern[128 + j];
                s.w += kern[192 + j];
            }
        }
        gTf[idx] = s;
    }
    for (int idx2 = tid; idx2 < 4096; idx2 += 256) {
        int a = idx2 >> 10, n = (idx2 >> 4) & 63, p0 = (idx2 & 15) * 2;
        float4 r = make_float4(0.f, 0.f, 0.f, 0.f);
        #pragma unroll
        for (int t = 0; t < 6; t++) {
            if ((n >> t) & 1) {
                r.x += kern[a * 64 + ((2 * p0 - 1 - t + 128) & 63)];
                r.y += kern[a * 64 + ((2 * p0 - 2 - t + 128) & 63)];
                r.z += kern[a * 64 + ((2 * p0 + 1 - t + 128) & 63)];
                r.w += kern[a * 64 + ((2 * p0 - t + 128) & 63)];
            }
        }
        gTq[idx2] = r;
    }
}

// ---------------------------------------------------------------------------
// wv radix-32: 13 chunks of 5 bits.
// P[0]=(a0,a1)@i0  P[1]=(a2,a3)@i0  P[2]=(a0,a1)@i1  P[3]=(a2,a3)@i1
// ---------------------------------------------------------------------------
__device__ __forceinline__ void rbm_wv32(u64 v, int lane,
                                         const ulonglong2* __restrict__ Tf,
                                         u64 P[4]) {
    P[0] = 0ull; P[1] = 0ull; P[2] = 0ull; P[3] = 0ull;
    int off = (-lane) & 63;
    #pragma unroll
    for (int c = 0; c < 13; c++) {
        unsigned n = (unsigned)(v >> (5 * c)) & 31u;
        int idx = (int)n * 64 + off;
        ulonglong2 A = Tf[idx];
        ulonglong2 B = Tf[idx ^ 32];
        P[0] = rbm_addx2(P[0], A.x);
        P[1] = rbm_addx2(P[1], A.y);
        P[2] = rbm_addx2(P[2], B.x);
        P[3] = rbm_addx2(P[3], B.y);
        off = (off + 5) & 63;
    }
}

// ---------------------------------------------------------------------------
// wh radix-64: 11 chunks of 6 bits per alpha; lane l accumulates packed
// outputs (2l, (2l-1)&63); table index p' = (l - 3c) & 31.
// SINGLE accumulator (R8 codegen: one address chain + immediate offsets).
// ---------------------------------------------------------------------------
__device__ __forceinline__ void rbm_wh64(const u64 h[4], int lane,
                                         const u64* __restrict__ Tq,
                                         float& wlo, float& whi) {
    u64 Q = 0ull;
    int p = lane;
    #pragma unroll
    for (int c = 0; c < 11; c++) {
        #pragma unroll
        for (int a = 0; a < 4; a++) {
            unsigned n = (unsigned)(h[a] >> (6 * c)) & 63u;
            Q = rbm_addx2(Q, Tq[(a * 64 + (int)n) * 32 + p]);
        }
        p = (p + 29) & 31;   // -3 mod 32
    }
    rbm_unpack2(Q, wlo, whi);   // wlo = wh[2l], whi = wh[(2l-1)&63]
}

__device__ __noinline__ float rbm_fe(u64 v, int lane,
                                     const ulonglong2* __restrict__ Tf,
                                     const float* __restrict__ csh, float bsc) {
    u64 P[4];
    rbm_wv32(v, lane, Tf, P);
    float ai0[4], ai1[4];
    rbm_unpack2(P[0], ai0[0], ai0[1]);
    rbm_unpack2(P[1], ai0[2], ai0[3]);
    rbm_unpack2(P[2], ai1[0], ai1[1]);
    rbm_unpack2(P[3], ai1[2], ai1[3]);
    float s = 0.0f;
    #pragma unroll
    for (int a = 0; a < 4; a++) {
        float ca = csh[a];
        s += rbm_softplus(ai0[a] + ca);
        s += rbm_softplus(ai1[a] + ca);
    }
    s = rbm_warp_sum(s);
    return -bsc * (float)__popcll(v) - s;
}

// ---------------------------------------------------------------------------
// Main kernel: one warp per sample pair (b, b+32768); 8 warps/block,
// 2 blocks/SM (96 KB smem each). R8 structure exactly.
// ---------------------------------------------------------------------------
__global__ void __launch_bounds__(TPB, 2)
rbm_gibbs_kernel(float* __restrict__ out,
                 const float* __restrict__ v_data,
                 const float* __restrict__ b_scalar,
                 const float* __restrict__ c_vector,
                 RbmKeys keys) {
    extern __shared__ char smem_dyn[];
    ulonglong2* Tf = (ulonglong2*)smem_dyn;
    u64*        Tq = (u64*)(smem_dyn + SMEM_TF_BYTES);
    __shared__ float  csh[4];
    __shared__ double wsum[WPB];

    const int tid  = threadIdx.x;
    const int lane = tid & 31;
    const int wid  = tid >> 5;

    {   // copy LUTs from global (L2-resident) to shared
        float4* sf = (float4*)smem_dyn;
        for (int i = tid; i < 32 * 64; i += TPB) sf[i] = gTf[i];
        float4* sq = (float4*)(smem_dyn + SMEM_TF_BYTES);
        for (int i = tid; i < 4096; i += TPB) sq[i] = gTq[i];
    }
    if (tid < 4) csh[tid] = c_vector[tid];
    __syncthreads();

    const float bsc = b_scalar[0];
    const int w  = blockIdx.x * WPB + wid;
    const int b0 = w;
    const int b1 = w + PAIRS;

    // Load v_data as bitmasks
    u64 v0, v1;
    {
        float a0 = v_data[(size_t)b0 * 64 + lane];
        float a1 = v_data[(size_t)b0 * 64 + lane + 32];
        unsigned lo = __ballot_sync(0xffffffffu, a0 != 0.0f);
        unsigned hi = __ballot_sync(0xffffffffu, a1 != 0.0f);
        v0 = (u64)lo | ((u64)hi << 32);
        float c0 = v_data[(size_t)b1 * 64 + lane];
        float c1 = v_data[(size_t)b1 * 64 + lane + 32];
        lo = __ballot_sync(0xffffffffu, c0 != 0.0f);
        hi = __ballot_sync(0xffffffffu, c1 != 0.0f);
        v1 = (u64)lo | ((u64)hi << 32);
    }

    const float fed0 = rbm_fe(v0, lane, Tf, csh, bsc);
    const float fed1 = rbm_fe(v1, lane, Tf, csh, bsc);

    const unsigned baseH = (unsigned)b0 * 256u;
    const unsigned baseV = (unsigned)b0 * 64u + (unsigned)lane;

    #pragma unroll 1
    for (int t = 0; t < GIBBS_K; t++) {
        u64 P0[4], P1[4];
        rbm_wv32(v0, lane, Tf, P0);
        rbm_wv32(v1, lane, Tf, P1);

        // e = exp(-(wv + c)); layout e[s][a*2+ii]
        float e0[8], e1[8];
        {
            float x, y;
            rbm_unpack2(P0[0], x, y); e0[0] = __expf(-(x + csh[0])); e0[2] = __expf(-(y + csh[1]));
            rbm_unpack2(P0[1], x, y); e0[4] = __expf(-(x + csh[2])); e0[6] = __expf(-(y + csh[3]));
            rbm_unpack2(P0[2], x, y); e0[1] = __expf(-(x + csh[0])); e0[3] = __expf(-(y + csh[1]));
            rbm_unpack2(P0[3], x, y); e0[5] = __expf(-(x + csh[2])); e0[7] = __expf(-(y + csh[3]));
            rbm_unpack2(P1[0], x, y); e1[0] = __expf(-(x + csh[0])); e1[2] = __expf(-(y + csh[1]));
            rbm_unpack2(P1[1], x, y); e1[4] = __expf(-(x + csh[2])); e1[6] = __expf(-(y + csh[3]));
            rbm_unpack2(P1[2], x, y); e1[1] = __expf(-(x + csh[0])); e1[3] = __expf(-(y + csh[1]));
            rbm_unpack2(P1[3], x, y); e1[5] = __expf(-(x + csh[2])); e1[7] = __expf(-(y + csh[3]));
        }

        const uint2 kh = keys.kh[t];
        const unsigned khs = keys.khs[t];
        u64 h0[4], h1[4];
        #pragma unroll
        for (int a = 0; a < 4; a++) {
            unsigned cA = baseH + (unsigned)(a * 64 + lane);
            unsigned cB = cA + 32u;
            unsigned rA0, rA1, rB0, rB1;
            rbm_tf2x32k(kh.x, kh.y, khs, cA, cA + HALF_H, rA0, rA1);
            rbm_tf2x32k(kh.x, kh.y, khs, cB, cB + HALF_H, rB0, rB1);
            unsigned l0 = __ballot_sync(0xffffffffu, rbm_draw(rA0, e0[a * 2 + 0]));
            unsigned g0 = __ballot_sync(0xffffffffu, rbm_draw(rB0, e0[a * 2 + 1]));
            unsigned l1 = __ballot_sync(0xffffffffu, rbm_draw(rA1, e1[a * 2 + 0]));
            unsigned g1 = __ballot_sync(0xffffffffu, rbm_draw(rB1, e1[a * 2 + 1]));
            h0[a] = (u64)l0 | ((u64)g0 << 32);
            h1[a] = (u64)l1 | ((u64)g1 << 32);
        }

        // wh packed at outputs (2l, 2l-1), then remap to (lane, lane+32)
        float w0lo, w0hi, w1lo, w1hi;
        rbm_wh64(h0, lane, Tq, w0lo, w0hi);
        rbm_wh64(h1, lane, Tq, w1lo, w1hi);

        const int src  = (lane + 1) >> 1;
        const int src2 = src + 16;          // shfl wraps mod 32
        float s0 = __shfl_sync(0xffffffffu, w0lo, src);
        float t0 = __shfl_sync(0xffffffffu, w0hi, src);
        float s1 = __shfl_sync(0xffffffffu, w0lo, src2);
        float t1 = __shfl_sync(0xffffffffu, w0hi, src2);
        float u0 = __shfl_sync(0xffffffffu, w1lo, src);
        float q0 = __shfl_sync(0xffffffffu, w1hi, src);
        float u1 = __shfl_sync(0xffffffffu, w1lo, src2);
        float q1 = __shfl_sync(0xffffffffu, w1hi, src2);
        const bool odd = (lane & 1);
        float wh00 = odd ? t0 : s0;   // sample0, i=lane
        float wh01 = odd ? t1 : s1;   // sample0, i=lane+32
        float wh10 = odd ? q0 : u0;   // sample1, i=lane
        float wh11 = odd ? q1 : u1;   // sample1, i=lane+32

        float ev00 = __expf(-(wh00 + bsc));
        float ev01 = __expf(-(wh01 + bsc));
        float ev10 = __expf(-(wh10 + bsc));
        float ev11 = __expf(-(wh11 + bsc));

        const uint2 kv = keys.kv[t];
        const unsigned kvs = keys.kvs[t];
        unsigned r00, r01, r10, r11;
        rbm_tf2x32k(kv.x, kv.y, kvs, baseV,       baseV + HALF_V,       r00, r01);
        rbm_tf2x32k(kv.x, kv.y, kvs, baseV + 32u, baseV + 32u + HALF_V, r10, r11);
        unsigned m0l = __ballot_sync(0xffffffffu, rbm_draw(r00, ev00));
        unsigned m0h = __ballot_sync(0xffffffffu, rbm_draw(r10, ev01));
        unsigned m1l = __ballot_sync(0xffffffffu, rbm_draw(r01, ev10));
        unsigned m1h = __ballot_sync(0xffffffffu, rbm_draw(r11, ev11));
        v0 = (u64)m0l | ((u64)m0h << 32);
        v1 = (u64)m1l | ((u64)m1h << 32);
    }

    const float fem0 = rbm_fe(v0, lane, Tf, csh, bsc);
    const float fem1 = rbm_fe(v1, lane, Tf, csh, bsc);
    const float diff = (fed0 - fem0) + (fed1 - fem1);

    if (lane == 0) wsum[wid] = (double)diff;
    __syncthreads();
    if (tid == 0) {
        double s = 0.0;
        #pragma unroll
        for (int i = 0; i < WPB; i++) s += wsum[i];
        atomicAdd(&g_rbm_sum, s);
        __threadfence();
        unsigned ticket = atomicAdd(&g_rbm_cnt, 1u);
        if (ticket == NBLOCKS - 1) {
            __threadfence();
            double total = atomicAdd(&g_rbm_sum, 0.0);
            out[0] = (float)(total / (double)BATCH);
            g_rbm_sum = 0.0;        // reset for next graph replay
            g_rbm_cnt = 0u;
        }
    }
}

// ---------------------------------------------------------------------------
// Host: replicate scan key-split chain: key(42); per step k,kh,kv = split(k,3)
// ---------------------------------------------------------------------------
extern "C" void kernel_launch(void* const* d_in, const int* in_sizes, int n_in,
                              void* d_out, int out_size) {
    const float* v_data   = (const float*)d_in[0];
    const float* kern     = (const float*)d_in[1];
    const float* b_scalar = (const float*)d_in[2];
    const float* c_vector = (const float*)d_in[3];

    RbmKeys keys;
    unsigned k0 = 0u, k1 = 42u;
    for (int t = 0; t < GIBBS_K; t++) {
        unsigned A0, B0, A1, B1, A2, B2;
        rbm_tf2x32_host(k0, k1, 0u, 3u, A0, B0);
        rbm_tf2x32_host(k0, k1, 1u, 4u, A1, B1);
        rbm_tf2x32_host(k0, k1, 2u, 5u, A2, B2);
        keys.kh[t]  = make_uint2(A2, B0);  // keys[1]
        keys.khs[t] = A2 ^ B0 ^ 0x1BD11BDAu;
        keys.kv[t]  = make_uint2(B1, B2);  // keys[2]
        keys.kvs[t] = B1 ^ B2 ^ 0x1BD11BDAu;
        k0 = A0; k1 = A1;                  // carried key
    }

    cudaFuncSetAttribute(rbm_gibbs_kernel,
                         cudaFuncAttributeMaxDynamicSharedMemorySize, SMEM_BYTES);

    rbm_build_tables<<<1, 256>>>(kern);
    rbm_gibbs_kernel<<<NBLOCKS, TPB, SMEM_BYTES>>>((float*)d_out, v_data,
                                                   b_scalar, c_vector, keys);
}